// round 10
// baseline (speedup 1.0000x reference)
#include <cuda_runtime.h>
#include <math.h>

#define BB 32
#define PP 64
#define LL 64
#define VV 32000
#define NROW (BB * PP)        // 2048
#define NBLK (NROW / 2)       // 1024 blocks, 2 rows each
#define CHUNK 8000            // bytes per bulk chunk (16 chunks per 128000B row)
#define NCHUNK 32             // 2 rows * 16 chunks
#define NSTAGE 3

// Scratch (no allocations allowed). Zero-initialized at module load.
// g_flag / g_done are reset by the last block each run (graph-replay safe).
__device__ uint2    g_mask[NROW];    // truth bitmask per (b,i)
__device__ int      g_flag[BB];      // DP-done flag per batch
__device__ float    g_sum[NROW];     // per-row sum over V
__device__ float    g_S[NROW];       // per-row sum at distinct argmins
__device__ int      g_m[NROW];       // per-row distinct argmin count
__device__ unsigned g_done;          // block completion counter

// ---- inline PTX helpers (mbarrier + bulk-async) ----
__device__ __forceinline__ unsigned smem_u32(const void* p) {
    unsigned a;
    asm("{ .reg .u64 t; cvta.to.shared.u64 t, %1; cvt.u32.u64 %0, t; }"
        : "=r"(a) : "l"(p));
    return a;
}
#define MBAR_INIT(addr, cnt) \
    asm volatile("mbarrier.init.shared.b64 [%0], %1;" :: "r"(addr), "r"(cnt) : "memory")
#define MBAR_EXPECT_TX(addr, bytes) \
    asm volatile("mbarrier.arrive.expect_tx.shared.b64 _, [%0], %1;" \
                 :: "r"(addr), "r"(bytes) : "memory")
#define MBAR_ARRIVE(addr) \
    asm volatile("mbarrier.arrive.shared.b64 _, [%0];" :: "r"(addr) : "memory")
#define MBAR_WAIT(addr, parity) do {                                           \
    asm volatile(                                                              \
        "{\n\t.reg .pred P1;\n\t"                                              \
        "WL_%=:\n\t"                                                           \
        "mbarrier.try_wait.parity.acquire.cta.shared::cta.b64 P1, [%0], %1, 0x989680;\n\t" \
        "@P1 bra.uni WD_%=;\n\t"                                               \
        "bra.uni WL_%=;\n\t"                                                   \
        "WD_%=:\n\t}"                                                          \
        :: "r"(addr), "r"(parity) : "memory");                                 \
} while (0)
#define BULK_G2S(dst, src, bytes, mbar) \
    asm volatile("cp.async.bulk.shared::cluster.global.mbarrier::complete_tx::bytes " \
                 "[%0], [%1], %2, [%3];" \
                 :: "r"(dst), "l"(src), "r"(bytes), "r"(mbar) : "memory")

// ---------------------------------------------------------------------------
// Single kernel, grid = 1024 x 256. Block q owns rows 2q, 2q+1.
// Streaming is done by cp.async.bulk into a 3-stage SMEM ring (full/empty
// mbarriers); 128KB/SM in flight -> DRAM-limited, not warp-MLP-limited.
//   blocks 0..31: warp 0 runs the edit-distance DP (excluded from the ring
//                 protocol via empty-count 224), publishes g_mask + g_flag.
//   producer    : tid 255 (expect_tx + bulk issue, 1 chunk ahead window=3).
//   epilogue    : flag wait, dedup gather (L2-hot), fp32 log1p finisher in
//                 the last block; resets flags for graph replay.
//
// Analytic collapse: q has 2 levels -> p1=e/D, p0=1/D, D=(V-m)+m*e.
// lnD = ln(V) + log1p(m*(e-1)/V);  kl = m*p1*(1-lnD) - (V-m)*p0*lnD
//                                      - p0*sumAll - (p1-p0)*Ssum
// ---------------------------------------------------------------------------
__global__ void __launch_bounds__(256, 8)
k_main(const float* __restrict__ outputs,
       const int* __restrict__ syms,
       const int* __restrict__ targets,
       const unsigned char* __restrict__ mask,
       float* __restrict__ out) {
    const unsigned FULL = 0xffffffffu;
    int q    = blockIdx.x;            // 0..1023
    int tid  = threadIdx.x;
    int lane = tid & 31, wid = tid >> 5;
    int rowA = 2 * q, rowB = 2 * q + 1;
    int b    = rowA >> 6;             // batch of both rows
    bool dpBlock = (q < BB);

    __shared__ __align__(16) float4 sbuf[NSTAGE * (CHUNK / 16)];   // 24000 B
    __shared__ __align__(8) unsigned long long s_mbar[2 * NSTAGE]; // full[3], empty[3]
    __shared__ float sred0[8], sred1[8];
    __shared__ int   stg[LL];
    __shared__ unsigned char str[LL];
    __shared__ float sS[2], sm[2];
    __shared__ float spart[256], scnt[256];
    __shared__ int   s_last;

    unsigned mb_full0  = smem_u32(&s_mbar[0]);
    unsigned mb_empty0 = smem_u32(&s_mbar[NSTAGE]);

    if (tid == 0) {
        int consumers = dpBlock ? 224 : 256;
        #pragma unroll
        for (int s = 0; s < NSTAGE; s++) {
            MBAR_INIT(mb_full0 + 8 * s, 1);
            MBAR_INIT(mb_empty0 + 8 * s, consumers);
        }
        asm volatile("fence.proxy.async.shared::cta;" ::: "memory");
    }
    __syncthreads();

    float acc0 = 0.0f, acc1 = 0.0f;

    // ---------------- DP (blocks 0..31, warp 0 only) ----------------
    if (dpBlock && wid == 0) {
        int bd = q;
        int j0 = 2 * lane, j1 = 2 * lane + 1;
        int tg0 = targets[bd * LL + j0];
        int tg1 = targets[bd * LL + j1];
        int mk0 = mask[bd * LL + j0];
        int mk1 = mask[bd * LL + j1];
        int s0  = syms[bd * PP + j0];
        int s1  = syms[bd * PP + j1];
        int tgm1 = __shfl_up_sync(FULL, tg1, 1);   // tg[j0-1]
        float p0 = (float)j0, p1 = (float)j1;      // row 0 (exact ints in fp32)

        for (int i = 0; i < PP; i++) {
            float d0, d1;
            if (i == 0) {
                d0 = p0; d1 = p1;
            } else {
                int im1 = i - 1;
                int sym = __shfl_sync(FULL, (im1 & 1) ? s1 : s0, im1 >> 1);
                float p1m = __shfl_up_sync(FULL, p1, 1);    // prev[j0-1]
                float tmp0 = (lane == 0) ? (float)i
                           : fminf(p1m + ((sym != tgm1) ? 1.0f : 0.0f), p0 + 1.0f);
                float tmp1 = fminf(p0 + ((sym != tg0) ? 1.0f : 0.0f), p1 + 1.0f);
                float v0 = tmp0 - (float)j0;
                float sB = fminf(v0, tmp1 - (float)j1);     // pair-inclusive
                float sc = sB;
                #pragma unroll
                for (int off = 1; off < 32; off <<= 1) {
                    float o = __shfl_up_sync(FULL, sc, off);
                    if (lane >= off) sc = fminf(sc, o);
                }
                float e = __shfl_up_sync(FULL, sc, 1);      // exclusive prefix
                if (lane == 0) e = INFINITY;
                d0 = (float)j0 + fminf(e, v0);
                d1 = (float)j1 + fminf(e, sB);
                p0 = d0; p1 = d1;
            }
            float md0 = mk0 ? d0 : INFINITY;
            float md1 = mk1 ? d1 : INFINITY;
            float mv = fminf(md0, md1);
            #pragma unroll
            for (int off = 16; off; off >>= 1)
                mv = fminf(mv, __shfl_xor_sync(FULL, mv, off));
            unsigned mE = __ballot_sync(FULL, md0 == mv);
            unsigned mO = __ballot_sync(FULL, md1 == mv);
            if (lane == 0) g_mask[bd * PP + i] = make_uint2(mE, mO);
        }
        __threadfence();
        if (lane == 0) atomicExch(&g_flag[bd], 1);
    } else {
        // ---------------- bulk-async pipelined stream -------------------
        const char* srcA = (const char*)(outputs + (size_t)rowA * VV);
        const char* srcB = (const char*)(outputs + (size_t)rowB * VV);
        int  tidc = dpBlock ? (tid - 32) : tid;
        int  nthr = dpBlock ? 224 : 256;
        bool producer = (tid == 255);

        if (producer) {
            #pragma unroll
            for (int c = 0; c < NSTAGE; c++) {      // prologue: fill all stages
                unsigned fb = mb_full0 + 8 * c;
                MBAR_EXPECT_TX(fb, CHUNK);
                const char* src = (c < 16) ? (srcA + (size_t)c * CHUNK)
                                           : (srcB + (size_t)(c - 16) * CHUNK);
                BULK_G2S(smem_u32(&sbuf[c * (CHUNK / 16)]), src, CHUNK, fb);
            }
        }

        for (int c = 0; c < NCHUNK; c++) {
            int s = c % NSTAGE, r = c / NSTAGE;
            MBAR_WAIT(mb_full0 + 8 * s, r & 1);
            float part = 0.0f;
            const float4* base = &sbuf[s * (CHUNK / 16)];
            for (int idx = tidc; idx < CHUNK / 16; idx += nthr) {
                float4 v = base[idx];
                part += (v.x + v.y) + (v.z + v.w);
            }
            if (c < 16) acc0 += part; else acc1 += part;
            MBAR_ARRIVE(mb_empty0 + 8 * s);
            if (producer && c + NSTAGE < NCHUNK) {
                int cn = c + NSTAGE;
                MBAR_WAIT(mb_empty0 + 8 * s, r & 1);
                unsigned fb = mb_full0 + 8 * s;
                MBAR_EXPECT_TX(fb, CHUNK);
                const char* src = (cn < 16) ? (srcA + (size_t)cn * CHUNK)
                                            : (srcB + (size_t)(cn - 16) * CHUNK);
                BULK_G2S(smem_u32(&sbuf[s * (CHUNK / 16)]), src, CHUNK, fb);
            }
        }
    }

    // block reduction of partial sums (DP warp contributes zeros)
    #pragma unroll
    for (int off = 16; off; off >>= 1) {
        acc0 += __shfl_down_sync(FULL, acc0, off);
        acc1 += __shfl_down_sync(FULL, acc1, off);
    }
    if (lane == 0) { sred0[wid] = acc0; sred1[wid] = acc1; }

    // -------- wait for this batch's DP flag (long set by now) --------
    if (tid == 0) {
        while (atomicAdd(&g_flag[b], 0) == 0) __nanosleep(64);
    }
    __syncthreads();
    __threadfence();

    // -------- per-row epilogue: dedup gather + plain stores ----------
    #pragma unroll
    for (int r = 0; r < 2; r++) {
        int row = r ? rowB : rowA;
        if (tid < LL) {
            stg[tid] = targets[b * LL + tid];
            uint2 m = g_mask[row];
            str[tid] = (unsigned char)((((tid & 1) ? m.y : m.x) >> (tid >> 1)) & 1);
        }
        __syncthreads();

        float c0 = 0.0f, n0 = 0.0f;
        if (tid < LL && str[tid]) {
            int tv = stg[tid];
            bool first = true;
            for (int k = 0; k < tid; k++)
                if (str[k] && stg[k] == tv) { first = false; break; }
            if (first) { c0 = outputs[(size_t)row * VV + tv]; n0 = 1.0f; }  // L2-hot
        }
        #pragma unroll
        for (int off = 16; off; off >>= 1) {
            c0 += __shfl_down_sync(FULL, c0, off);
            n0 += __shfl_down_sync(FULL, n0, off);
        }
        if (tid < LL && lane == 0) { sS[wid] = c0; sm[wid] = n0; }
        __syncthreads();

        if (tid == 0) {
            const float* sr = r ? sred1 : sred0;
            float s = 0.0f;
            #pragma unroll
            for (int w = 0; w < 8; w++) s += sr[w];
            g_sum[row] = s;
            g_S[row]   = sS[0] + sS[1];
            g_m[row]   = (int)(sm[0] + sm[1]);
        }
        __syncthreads();
    }

    // ---------------- last-block finisher (all fp32) ----------------
    if (tid == 0) {
        __threadfence();
        unsigned prev = atomicAdd(&g_done, 1u);
        s_last = (prev == (unsigned)(gridDim.x - 1));
    }
    __syncthreads();
    if (!s_last) return;

    const float E1f  = 2.71828182845904523f;
    const float EM1V = 1.71828182845904523f / 32000.0f;
    const float LNV  = 10.37349118f;                 // ln(32000)
    int bb = tid >> 3, sl = tid & 7;

    float kacc = 0.0f, cnt = 0.0f;
    #pragma unroll
    for (int k = 0; k < 8; k++) {
        int i  = sl + 8 * k;
        int bp = bb * PP + i;
        if (mask[bb * LL + i]) {
            float mm  = (float)g_m[bp];
            float D   = ((float)VV - mm) + mm * E1f;
            float p0  = 1.0f / D;
            float p1  = E1f * p0;
            float x   = mm * EM1V;
            float l1p = x * (1.0f + x * (-0.5f + x * (0.33333333f + x * -0.25f)));
            float lnD = LNV + l1p;
            kacc += mm * p1 * (1.0f - lnD) - ((float)VV - mm) * p0 * lnD
                  - p0 * g_sum[bp] - (p1 - p0) * g_S[bp];
            cnt  += 1.0f;
        }
    }
    spart[tid] = kacc; scnt[tid] = cnt;
    __syncthreads();

    if (tid < BB) {
        float s = 0.0f, w = 0.0f;
        #pragma unroll
        for (int k = 0; k < 8; k++) { s += spart[tid * 8 + k]; w += scnt[tid * 8 + k]; }
        float pb = s / (w + 1e-13f);
        float ne = (w > 0.0f) ? 1.0f : 0.0f;
        #pragma unroll
        for (int off = 16; off; off >>= 1) {
            pb += __shfl_down_sync(FULL, pb, off);
            ne += __shfl_down_sync(FULL, ne, off);
        }
        if (tid == 0) out[0] = pb / (ne + 1e-13f);
        g_flag[tid] = 0;                   // reset handshake for next replay
        if (tid == 0) g_done = 0u;
    }
}

// ---------------------------------------------------------------------------
extern "C" void kernel_launch(void* const* d_in, const int* in_sizes, int n_in,
                              void* d_out, int out_size) {
    const float*         outputs = (const float*)d_in[0];
    const int*           syms    = (const int*)d_in[1];
    const int*           targets = (const int*)d_in[2];
    const unsigned char* mask    = (const unsigned char*)d_in[3];

    k_main<<<NBLK, 256>>>(outputs, syms, targets, mask, (float*)d_out);
}

// round 11
// speedup vs baseline: 1.0717x; 1.0717x over previous
#include <cuda_runtime.h>
#include <math.h>

#define BB 32
#define PP 64
#define LL 64
#define VV 32000
#define NROW (BB * PP)       // 2048

// Scratch (no allocations allowed). Zero-initialized at module load.
// g_flag / g_done are reset by the last block each run (graph-replay safe).
__device__ uint2    g_mask[NROW];    // truth bitmask per (b,i)
__device__ int      g_flag[BB];      // DP-done flag per batch
__device__ float    g_sum[NROW];     // per-row sum over V
__device__ float    g_S[NROW];       // per-row sum at distinct argmins
__device__ int      g_m[NROW];       // per-row distinct argmin count
__device__ unsigned g_done;          // block completion counter

// ---------------------------------------------------------------------------
// Single kernel, grid = 2048 x 256: ONE ROW PER BLOCK (finest granularity —
// measured fastest streaming config, R5). Order: (DP for blocks 0..31) ->
// stream own row (unroll-4 LDG) -> flag-wait (DP hidden under stream) ->
// dedup-gather epilogue -> last-block fp32 finisher.
//
// Analytic collapse: q has 2 levels -> p1=e/D, p0=1/D, D=(V-m)+m*e.
// lnD = ln(V) + log1p(m*(e-1)/V);  ln p1 = 1-lnD;  ln p0 = -lnD.
// kl = m*p1*(1-lnD) - (V-m)*p0*lnD - p0*sumAll - (p1-p0)*Ssum
// ---------------------------------------------------------------------------
__global__ void __launch_bounds__(256, 8)
k_main(const float* __restrict__ outputs,
       const int* __restrict__ syms,
       const int* __restrict__ targets,
       const unsigned char* __restrict__ mask,
       float* __restrict__ out) {
    const unsigned FULL = 0xffffffffu;
    int bp   = blockIdx.x;            // 0..2047 (row id)
    int b    = bp >> 6;
    int tid  = threadIdx.x;
    int lane = tid & 31, wid = tid >> 5;

    // ---------------- DP (blocks 0..31, warp 0 only) ----------------
    if (bp < BB && wid == 0) {
        int bd = bp;
        int j0 = 2 * lane, j1 = 2 * lane + 1;
        int tg0 = targets[bd * LL + j0];
        int tg1 = targets[bd * LL + j1];
        int mk0 = mask[bd * LL + j0];
        int mk1 = mask[bd * LL + j1];
        int s0  = syms[bd * PP + j0];
        int s1  = syms[bd * PP + j1];
        int tgm1 = __shfl_up_sync(FULL, tg1, 1);   // tg[j0-1]
        float p0 = (float)j0, p1 = (float)j1;      // row 0 (exact ints in fp32)

        for (int i = 0; i < PP; i++) {
            float d0, d1;
            if (i == 0) {
                d0 = p0; d1 = p1;
            } else {
                int im1 = i - 1;
                int sym = __shfl_sync(FULL, (im1 & 1) ? s1 : s0, im1 >> 1);
                float p1m = __shfl_up_sync(FULL, p1, 1);    // prev[j0-1]
                float tmp0 = (lane == 0) ? (float)i
                           : fminf(p1m + ((sym != tgm1) ? 1.0f : 0.0f), p0 + 1.0f);
                float tmp1 = fminf(p0 + ((sym != tg0) ? 1.0f : 0.0f), p1 + 1.0f);
                float v0 = tmp0 - (float)j0;
                float sB = fminf(v0, tmp1 - (float)j1);     // pair-inclusive
                float sc = sB;
                #pragma unroll
                for (int off = 1; off < 32; off <<= 1) {
                    float o = __shfl_up_sync(FULL, sc, off);
                    if (lane >= off) sc = fminf(sc, o);
                }
                float e = __shfl_up_sync(FULL, sc, 1);      // exclusive prefix
                if (lane == 0) e = INFINITY;
                d0 = (float)j0 + fminf(e, v0);
                d1 = (float)j1 + fminf(e, sB);
                p0 = d0; p1 = d1;
            }
            float md0 = mk0 ? d0 : INFINITY;
            float md1 = mk1 ? d1 : INFINITY;
            float mv = fminf(md0, md1);
            #pragma unroll
            for (int off = 16; off; off >>= 1)
                mv = fminf(mv, __shfl_xor_sync(FULL, mv, off));
            unsigned mE = __ballot_sync(FULL, md0 == mv);
            unsigned mO = __ballot_sync(FULL, md1 == mv);
            if (lane == 0) g_mask[bd * PP + i] = make_uint2(mE, mO);
        }
        __threadfence();
        if (lane == 0) atomicExch(&g_flag[bd], 1);
    }

    // ---------------- rowsum (HBM-bound, fp32, unroll 4) ------------
    const float4* row4 = (const float4*)(outputs + (size_t)bp * VV);
    float acc = 0.0f;
    {
        int idx = tid;
        #pragma unroll 4
        for (int k = 0; k < 31; k++, idx += 256) {      // 31*256 = 7936 float4
            float4 v = row4[idx];
            acc += (v.x + v.y) + (v.z + v.w);
        }
        if (tid < (VV / 4 - 7936)) {                    // tail: 64 float4
            float4 v = row4[7936 + tid];
            acc += (v.x + v.y) + (v.z + v.w);
        }
    }
    #pragma unroll
    for (int off = 16; off; off >>= 1)
        acc += __shfl_down_sync(FULL, acc, off);
    __shared__ float sred[8];
    if (lane == 0) sred[wid] = acc;

    // ---------------- wait for this batch's DP mask (hidden) --------
    if (tid == 0) {
        while (atomicAdd(&g_flag[b], 0) == 0) __nanosleep(64);
    }
    __syncthreads();
    __threadfence();

    // ---------------- dedup gather of distinct argmin symbols ------
    __shared__ int stg[LL];
    __shared__ unsigned char str[LL];
    if (tid < LL) {
        stg[tid] = targets[b * LL + tid];
        uint2 m = g_mask[bp];
        str[tid] = (unsigned char)((((tid & 1) ? m.y : m.x) >> (tid >> 1)) & 1);
    }
    __syncthreads();

    float contrib = 0.0f, cm = 0.0f;
    if (tid < LL && str[tid]) {
        int tv = stg[tid];
        bool first = true;
        for (int k = 0; k < tid; k++)
            if (str[k] && stg[k] == tv) { first = false; break; }
        if (first) {
            contrib = outputs[(size_t)bp * VV + tv];   // L2-hot: row just streamed
            cm = 1.0f;
        }
    }
    #pragma unroll
    for (int off = 16; off; off >>= 1) {
        contrib += __shfl_down_sync(FULL, contrib, off);
        cm      += __shfl_down_sync(FULL, cm, off);
    }
    __shared__ float sc2[2], sm2[2];
    if (tid < LL && lane == 0) { sc2[wid] = contrib; sm2[wid] = cm; }
    __syncthreads();

    if (tid == 0) {
        float s = 0.0f;
        #pragma unroll
        for (int w = 0; w < 8; w++) s += sred[w];
        g_sum[bp] = s;
        g_S[bp]   = sc2[0] + sc2[1];
        g_m[bp]   = (int)(sm2[0] + sm2[1]);
    }

    // ---------------- last-block finisher (all fp32) ----------------
    __shared__ int s_last;
    if (tid == 0) {
        __threadfence();
        unsigned prev = atomicAdd(&g_done, 1u);
        s_last = (prev == (unsigned)(gridDim.x - 1));
    }
    __syncthreads();
    if (!s_last) return;

    // thread t = bb*8 + s : batch bb, rows i = s + 8*k (k<8). Deterministic.
    const float E1f  = 2.71828182845904523f;
    const float EM1V = 1.71828182845904523f / 32000.0f;
    const float LNV  = 10.37349118f;                 // ln(32000)
    int bb = tid >> 3, sl = tid & 7;

    float kacc = 0.0f, cnt = 0.0f;
    #pragma unroll
    for (int k = 0; k < 8; k++) {
        int i  = sl + 8 * k;
        int r  = bb * PP + i;
        if (mask[bb * LL + i]) {
            float mm  = (float)g_m[r];
            float D   = ((float)VV - mm) + mm * E1f;
            float p0  = 1.0f / D;
            float p1  = E1f * p0;
            float x   = mm * EM1V;
            float l1p = x * (1.0f + x * (-0.5f + x * (0.33333333f + x * -0.25f)));
            float lnD = LNV + l1p;
            kacc += mm * p1 * (1.0f - lnD) - ((float)VV - mm) * p0 * lnD
                  - p0 * g_sum[r] - (p1 - p0) * g_S[r];
            cnt  += 1.0f;
        }
    }
    __shared__ float spart[256], scnt[256];
    spart[tid] = kacc; scnt[tid] = cnt;
    __syncthreads();

    if (tid < BB) {
        float s = 0.0f, w = 0.0f;
        #pragma unroll
        for (int k = 0; k < 8; k++) { s += spart[tid * 8 + k]; w += scnt[tid * 8 + k]; }
        float pb = s / (w + 1e-13f);
        float ne = (w > 0.0f) ? 1.0f : 0.0f;
        #pragma unroll
        for (int off = 16; off; off >>= 1) {
            pb += __shfl_down_sync(FULL, pb, off);
            ne += __shfl_down_sync(FULL, ne, off);
        }
        if (tid == 0) out[0] = pb / (ne + 1e-13f);
        g_flag[tid] = 0;                   // reset handshake for next replay
        if (tid == 0) g_done = 0u;
    }
}

// ---------------------------------------------------------------------------
extern "C" void kernel_launch(void* const* d_in, const int* in_sizes, int n_in,
                              void* d_out, int out_size) {
    const float*         outputs = (const float*)d_in[0];
    const int*           syms    = (const int*)d_in[1];
    const int*           targets = (const int*)d_in[2];
    const unsigned char* mask    = (const unsigned char*)d_in[3];

    k_main<<<NROW, 256>>>(outputs, syms, targets, mask, (float*)d_out);
}

// round 12
// speedup vs baseline: 1.1211x; 1.0461x over previous
#include <cuda_runtime.h>
#include <math.h>

#define BB 32
#define PP 64
#define LL 64
#define VV 32000
#define NROW (BB * PP)       // 2048

// Scratch (no allocations allowed). Zero-initialized at module load.
// g_flag / g_done are reset by the last block each run (graph-replay safe).
__device__ uint2    g_mask[NROW];    // truth bitmask per (b,i)
__device__ int      g_flag[BB];      // DP-done flag per batch
__device__ float    g_sum[NROW];     // per-row sum over V
__device__ float    g_S[NROW];       // per-row sum at distinct argmins
__device__ int      g_m[NROW];       // per-row distinct argmin count
__device__ unsigned g_done;          // block completion counter

// ---------------------------------------------------------------------------
// Single kernel, grid = 2048 x 256, one row per block (measured-best shape).
// R12 delta vs R11: stream loop uses 4 independent accumulators (breaks the
// FADD chain -> front-batched LDGs, higher MLP_eff) and __ldcs (evict-first;
// 262MB single-use stream should not occupy L2 ways).
// Order: (DP for blocks 0..31) -> stream own row -> flag-wait (DP hidden) ->
// dedup-gather epilogue -> last-block fp32 log1p finisher.
//
// Analytic collapse: q has 2 levels -> p1=e/D, p0=1/D, D=(V-m)+m*e.
// lnD = ln(V) + log1p(m*(e-1)/V);  ln p1 = 1-lnD;  ln p0 = -lnD.
// kl = m*p1*(1-lnD) - (V-m)*p0*lnD - p0*sumAll - (p1-p0)*Ssum
// ---------------------------------------------------------------------------
__global__ void __launch_bounds__(256, 8)
k_main(const float* __restrict__ outputs,
       const int* __restrict__ syms,
       const int* __restrict__ targets,
       const unsigned char* __restrict__ mask,
       float* __restrict__ out) {
    const unsigned FULL = 0xffffffffu;
    int bp   = blockIdx.x;            // 0..2047 (row id)
    int b    = bp >> 6;
    int tid  = threadIdx.x;
    int lane = tid & 31, wid = tid >> 5;

    // ---------------- DP (blocks 0..31, warp 0 only) ----------------
    if (bp < BB && wid == 0) {
        int bd = bp;
        int j0 = 2 * lane, j1 = 2 * lane + 1;
        int tg0 = targets[bd * LL + j0];
        int tg1 = targets[bd * LL + j1];
        int mk0 = mask[bd * LL + j0];
        int mk1 = mask[bd * LL + j1];
        int s0  = syms[bd * PP + j0];
        int s1  = syms[bd * PP + j1];
        int tgm1 = __shfl_up_sync(FULL, tg1, 1);   // tg[j0-1]
        float p0 = (float)j0, p1 = (float)j1;      // row 0 (exact ints in fp32)

        for (int i = 0; i < PP; i++) {
            float d0, d1;
            if (i == 0) {
                d0 = p0; d1 = p1;
            } else {
                int im1 = i - 1;
                int sym = __shfl_sync(FULL, (im1 & 1) ? s1 : s0, im1 >> 1);
                float p1m = __shfl_up_sync(FULL, p1, 1);    // prev[j0-1]
                float tmp0 = (lane == 0) ? (float)i
                           : fminf(p1m + ((sym != tgm1) ? 1.0f : 0.0f), p0 + 1.0f);
                float tmp1 = fminf(p0 + ((sym != tg0) ? 1.0f : 0.0f), p1 + 1.0f);
                float v0 = tmp0 - (float)j0;
                float sB = fminf(v0, tmp1 - (float)j1);     // pair-inclusive
                float sc = sB;
                #pragma unroll
                for (int off = 1; off < 32; off <<= 1) {
                    float o = __shfl_up_sync(FULL, sc, off);
                    if (lane >= off) sc = fminf(sc, o);
                }
                float e = __shfl_up_sync(FULL, sc, 1);      // exclusive prefix
                if (lane == 0) e = INFINITY;
                d0 = (float)j0 + fminf(e, v0);
                d1 = (float)j1 + fminf(e, sB);
                p0 = d0; p1 = d1;
            }
            float md0 = mk0 ? d0 : INFINITY;
            float md1 = mk1 ? d1 : INFINITY;
            float mv = fminf(md0, md1);
            #pragma unroll
            for (int off = 16; off; off >>= 1)
                mv = fminf(mv, __shfl_xor_sync(FULL, mv, off));
            unsigned mE = __ballot_sync(FULL, md0 == mv);
            unsigned mO = __ballot_sync(FULL, md1 == mv);
            if (lane == 0) g_mask[bd * PP + i] = make_uint2(mE, mO);
        }
        __threadfence();
        if (lane == 0) atomicExch(&g_flag[bd], 1);
    }

    // ------- rowsum: 4 accumulators, unroll 8, __ldcs (evict-first) -------
    const float4* row4 = (const float4*)(outputs + (size_t)bp * VV);
    float a0 = 0.0f, a1 = 0.0f, a2 = 0.0f, a3 = 0.0f;
    {
        int idx = tid;
        #pragma unroll 8
        for (int k = 0; k < 31; k++, idx += 256) {      // 31*256 = 7936 float4
            float4 v = __ldcs(row4 + idx);
            float s = (v.x + v.y) + (v.z + v.w);
            switch (k & 3) {
                case 0: a0 += s; break;
                case 1: a1 += s; break;
                case 2: a2 += s; break;
                default: a3 += s; break;
            }
        }
        if (tid < (VV / 4 - 7936)) {                    // tail: 64 float4
            float4 v = __ldcs(row4 + 7936 + tid);
            a0 += (v.x + v.y) + (v.z + v.w);
        }
    }
    float acc = (a0 + a1) + (a2 + a3);
    #pragma unroll
    for (int off = 16; off; off >>= 1)
        acc += __shfl_down_sync(FULL, acc, off);
    __shared__ float sred[8];
    if (lane == 0) sred[wid] = acc;

    // ---------------- wait for this batch's DP mask (hidden) --------
    if (tid == 0) {
        while (atomicAdd(&g_flag[b], 0) == 0) __nanosleep(64);
    }
    __syncthreads();
    __threadfence();

    // ---------------- dedup gather of distinct argmin symbols ------
    __shared__ int stg[LL];
    __shared__ unsigned char str[LL];
    if (tid < LL) {
        stg[tid] = targets[b * LL + tid];
        uint2 m = g_mask[bp];
        str[tid] = (unsigned char)((((tid & 1) ? m.y : m.x) >> (tid >> 1)) & 1);
    }
    __syncthreads();

    float contrib = 0.0f, cm = 0.0f;
    if (tid < LL && str[tid]) {
        int tv = stg[tid];
        bool first = true;
        for (int k = 0; k < tid; k++)
            if (str[k] && stg[k] == tv) { first = false; break; }
        if (first) {
            contrib = outputs[(size_t)bp * VV + tv];
            cm = 1.0f;
        }
    }
    #pragma unroll
    for (int off = 16; off; off >>= 1) {
        contrib += __shfl_down_sync(FULL, contrib, off);
        cm      += __shfl_down_sync(FULL, cm, off);
    }
    __shared__ float sc2[2], sm2[2];
    if (tid < LL && lane == 0) { sc2[wid] = contrib; sm2[wid] = cm; }
    __syncthreads();

    if (tid == 0) {
        float s = 0.0f;
        #pragma unroll
        for (int w = 0; w < 8; w++) s += sred[w];
        g_sum[bp] = s;
        g_S[bp]   = sc2[0] + sc2[1];
        g_m[bp]   = (int)(sm2[0] + sm2[1]);
    }

    // ---------------- last-block finisher (all fp32) ----------------
    __shared__ int s_last;
    if (tid == 0) {
        __threadfence();
        unsigned prev = atomicAdd(&g_done, 1u);
        s_last = (prev == (unsigned)(gridDim.x - 1));
    }
    __syncthreads();
    if (!s_last) return;

    // thread t = bb*8 + s : batch bb, rows i = s + 8*k (k<8). Deterministic.
    const float E1f  = 2.71828182845904523f;
    const float EM1V = 1.71828182845904523f / 32000.0f;
    const float LNV  = 10.37349118f;                 // ln(32000)
    int bb = tid >> 3, sl = tid & 7;

    float kacc = 0.0f, cnt = 0.0f;
    #pragma unroll
    for (int k = 0; k < 8; k++) {
        int i = sl + 8 * k;
        int r = bb * PP + i;
        if (mask[bb * LL + i]) {
            float mm  = (float)g_m[r];
            float D   = ((float)VV - mm) + mm * E1f;
            float p0  = 1.0f / D;
            float p1  = E1f * p0;
            float x   = mm * EM1V;
            float l1p = x * (1.0f + x * (-0.5f + x * (0.33333333f + x * -0.25f)));
            float lnD = LNV + l1p;
            kacc += mm * p1 * (1.0f - lnD) - ((float)VV - mm) * p0 * lnD
                  - p0 * g_sum[r] - (p1 - p0) * g_S[r];
            cnt  += 1.0f;
        }
    }
    __shared__ float spart[256], scnt[256];
    spart[tid] = kacc; scnt[tid] = cnt;
    __syncthreads();

    if (tid < BB) {
        float s = 0.0f, w = 0.0f;
        #pragma unroll
        for (int k = 0; k < 8; k++) { s += spart[tid * 8 + k]; w += scnt[tid * 8 + k]; }
        float pb = s / (w + 1e-13f);
        float ne = (w > 0.0f) ? 1.0f : 0.0f;
        #pragma unroll
        for (int off = 16; off; off >>= 1) {
            pb += __shfl_down_sync(FULL, pb, off);
            ne += __shfl_down_sync(FULL, ne, off);
        }
        if (tid == 0) out[0] = pb / (ne + 1e-13f);
        g_flag[tid] = 0;                   // reset handshake for next replay
        if (tid == 0) g_done = 0u;
    }
}

// ---------------------------------------------------------------------------
extern "C" void kernel_launch(void* const* d_in, const int* in_sizes, int n_in,
                              void* d_out, int out_size) {
    const float*         outputs = (const float*)d_in[0];
    const int*           syms    = (const int*)d_in[1];
    const int*           targets = (const int*)d_in[2];
    const unsigned char* mask    = (const unsigned char*)d_in[3];

    k_main<<<NROW, 256>>>(outputs, syms, targets, mask, (float*)d_out);
}